// round 6
// baseline (speedup 1.0000x reference)
#include <cuda_runtime.h>

// PixelWiseNet: out[h,w] = bias + sum_{c,k} p_a[c,k]*relu(x[c,h,w]*rowsum(M[c]) + bias_c[c] - p_t[c,k])
// C=3, H=W=1024, K=16.  Output [1024,1024] f32.
//
// Algebra: a*relu(s-t) = ap*max(u,tp) + cst  with ap=a*|scale|, u=x*sgn(scale),
//          tp=(t-bc)/|scale|, cst=a*(bc-t).  Per channel, g_c(u)=Σ_k ap*max(u,tp_k)
//          is continuous piecewise-linear with 16 breakpoints:
//            sort tp ascending; in segment j (# thresholds <= u):
//            g_c(u) = u*A[j] + B[j],  A[j]=Σ_{r<j} ap_r (sorted),  B[j]=Σ_{r>=j} ap_r*tp_r.
//          out = CONST + Σ_c g_c(u_c),  CONST = bias + Σ cst.
// Hot loop per pixel-channel: 5-step branchless binary search + 1 FFMA
// (~17 issue slots) instead of 16 FMNMX + 16 FFMA + LDS (~40 slots).

#define C 3
#define K 16
#define HW (1024 * 1024)
#define N4 (HW / 4)
#define THREADS 256
#define BLOCKS (N4 / THREADS)    // 1024

__global__ __launch_bounds__(THREADS)
void pixelwise_kernel(const float4* __restrict__ x,
                      const float* __restrict__ M,
                      const float* __restrict__ p_a,
                      const float* __restrict__ p_t,
                      const float* __restrict__ bias_c,
                      const float* __restrict__ bias,
                      float4* __restrict__ out) {
    __shared__ float  sh_tp[C * K];        // raw transformed thresholds
    __shared__ float  sh_ap[C * K];        // raw transformed slopes
    __shared__ float  sh_st[C * K];        // sorted thresholds per channel
    __shared__ float  sh_sa[C * K];        // slopes in sorted order
    __shared__ float2 sh_AB[C * (K + 1)];  // (A_j, B_j) per channel, 17 segments
    __shared__ float  sh_xsign[C];
    __shared__ float  sh_const;
    __shared__ float  sh_partial[64];

    int tid = threadIdx.x;

    // ---- stage + transform params (48 threads) ----
    if (tid < C * K) {
        int c = tid / K;
        float scale = M[c * 3 + 0] + M[c * 3 + 1] + M[c * 3 + 2];
        float sa = fabsf(scale);
        float a = p_a[tid], t = p_t[tid], bc = bias_c[c];
        float ap, tp, cst;
        if (sa > 0.0f) {
            ap  = a * sa;
            tp  = (t - bc) / sa;
            cst = a * (bc - t);
        } else {
            ap = 0.0f; tp = 0.0f;
            cst = a * (fmaxf(bc, t) - t);
        }
        sh_tp[tid] = tp;
        sh_ap[tid] = ap;
        sh_partial[tid] = cst;
        if (tid < C) sh_xsign[tid] = (scale >= 0.0f) ? 1.0f : -1.0f;
    } else if (tid < 64) {
        sh_partial[tid] = 0.0f;
    }
    __syncthreads();

    // ---- rank-sort thresholds per channel (48 threads) + CONST reduce (warp 1) ----
    if (tid < C * K) {
        int c = tid / K, k = tid % K;
        float my_t = sh_tp[tid];
        int rank = 0;
        #pragma unroll
        for (int j = 0; j < K; j++) {
            float o = sh_tp[c * K + j];
            rank += (o < my_t || (o == my_t && j < k)) ? 1 : 0;
        }
        sh_st[c * K + rank] = my_t;
        sh_sa[c * K + rank] = sh_ap[tid];
    }
    if (tid >= 32 && tid < 64) {
        float v = sh_partial[tid - 32] + sh_partial[tid];
        #pragma unroll
        for (int o = 16; o; o >>= 1) v += __shfl_xor_sync(0xffffffffu, v, o);
        if (tid == 32) sh_const = v + bias[0];
    }
    __syncthreads();

    // ---- build segment tables (51 threads) ----
    if (tid < C * (K + 1)) {
        int c = tid / (K + 1), j = tid % (K + 1);
        float A = 0.0f, B = 0.0f;
        #pragma unroll
        for (int r = 0; r < K; r++) {
            float sv = sh_sa[c * K + r];
            if (r < j) A += sv;
            else       B += sv * sh_st[c * K + r];
        }
        if (c == 0) B += sh_const;   // fold global constant into channel 0
        sh_AB[tid] = make_float2(A, B);
    }
    __syncthreads();

    // ---- main: 4 pixels per thread ----
    int i = blockIdx.x * THREADS + tid;

    float xs0 = sh_xsign[0], xs1 = sh_xsign[1], xs2 = sh_xsign[2];
    float4 v0 = x[i];
    float4 v1 = x[N4 + i];
    float4 v2 = x[2 * N4 + i];

    float u[C][4];
    u[0][0] = v0.x * xs0; u[0][1] = v0.y * xs0; u[0][2] = v0.z * xs0; u[0][3] = v0.w * xs0;
    u[1][0] = v1.x * xs1; u[1][1] = v1.y * xs1; u[1][2] = v1.z * xs1; u[1][3] = v1.w * xs1;
    u[2][0] = v2.x * xs2; u[2][1] = v2.y * xs2; u[2][2] = v2.z * xs2; u[2][3] = v2.w * xs2;

    float accA[4] = {0.f, 0.f, 0.f, 0.f};   // FFMA chains
    float accB[4] = {0.f, 0.f, 0.f, 0.f};   // B-term adds

    #pragma unroll
    for (int c = 0; c < C; c++) {
        const float* st = &sh_st[c * K];
        const float2* ab = &sh_AB[c * (K + 1)];
        #pragma unroll
        for (int p = 0; p < 4; p++) {
            float uu = u[c][p];
            // j = #{r : st[r] <= uu}, branchless binary search (pred-as-data SELs)
            int j;
            j  = (uu >= st[7])     ? 8 : 0;
            j += (uu >= st[j + 3]) ? 4 : 0;
            j += (uu >= st[j + 1]) ? 2 : 0;
            j += (uu >= st[j])     ? 1 : 0;
            j += (uu >= st[j])     ? 1 : 0;   // fix-up: distinguishes count 15 vs 16
            float2 AB = ab[j];
            accA[p] = fmaf(uu, AB.x, accA[p]);
            accB[p] += AB.y;
        }
    }

    float4 r;
    r.x = accA[0] + accB[0];
    r.y = accA[1] + accB[1];
    r.z = accA[2] + accB[2];
    r.w = accA[3] + accB[3];
    out[i] = r;
}

extern "C" void kernel_launch(void* const* d_in, const int* in_sizes, int n_in,
                              void* d_out, int out_size) {
    const float4* x      = (const float4*)d_in[0];
    const float*  M      = (const float*)d_in[1];
    const float*  p_a    = (const float*)d_in[2];
    const float*  p_t    = (const float*)d_in[3];
    const float*  bias_c = (const float*)d_in[4];
    const float*  bias   = (const float*)d_in[5];
    float4* out = (float4*)d_out;

    pixelwise_kernel<<<BLOCKS, THREADS>>>(x, M, p_a, p_t, bias_c, bias, out);
}